// round 4
// baseline (speedup 1.0000x reference)
#include <cuda_runtime.h>

#define BATCH 16
#define HW (1 << 20)
#define CB 4096                 // coarse bins (q >> 4)
#define FBITS 4                 // fine bins = 16 (q & 15)
#define CHUNKS 64
#define NT 256

// percentile ranks, n = 1048576 (linear interp):
// blk: 0.25*v[10485] + 0.75*v[10486] ; wht: 0.75*v[1038089] + 0.25*v[1038090]
#define RANK0 10485u
#define RANK1 10486u
#define RANK2 1038089u
#define RANK3 1038090u

// ---------------- device scratch ----------------
__device__ unsigned short g_Y16[(size_t)BATCH * HW];   // 32 MB quantized luma
__device__ unsigned g_hist[BATCH][CB];                 // coarse hists
__device__ unsigned g_hist2[BATCH][4][16];             // fine hists (tiny)
__device__ int      g_tbin[BATCH][4];
__device__ int      g_trank[BATCH][4];

__device__ __forceinline__ float4 ldcs4(const float4* p) { return __ldcs(p); }

// ------------- kernel 1: Y16 + coarse hist (zeroes g_hist2 for this replay) -------------
// Two independent streams per thread for doubled MLP; 32-reg cap for full occupancy.
__global__ void __launch_bounds__(NT, 8) k_yhist(const float* __restrict__ img,
                                                 const float* __restrict__ mat) {
    __shared__ unsigned sh[CB];
    const int b = blockIdx.y;
    const int chunk = blockIdx.x;

    if (blockIdx.x == 0 && threadIdx.x < 64)
        ((unsigned*)g_hist2[b])[threadIdx.x] = 0u;

    for (int j = threadIdx.x; j < CB; j += NT) sh[j] = 0u;
    __syncthreads();

    const float c0 = mat[0], c1 = mat[1], c2 = mat[2];
    const size_t base = (size_t)b * 3 * HW;
    const float4* __restrict__ R  = (const float4*)(img + base);
    const float4* __restrict__ G  = (const float4*)(img + base + HW);
    const float4* __restrict__ Bc = (const float4*)(img + base + 2 * (size_t)HW);
    uint2* __restrict__ Y = (uint2*)(g_Y16 + (size_t)b * HW);

    const int per_cta = (HW / 4) / CHUNKS;   // 4096 float4
    const int half = per_cta / 2;            // 2048
    const int offA = chunk * per_cta;
    const int offB = offA + half;

    #pragma unroll 2
    for (int i = threadIdx.x; i < half; i += NT) {
        float4 rA = ldcs4(R + offA + i);
        float4 gA = ldcs4(G + offA + i);
        float4 vA = ldcs4(Bc + offA + i);
        float4 rB = ldcs4(R + offB + i);
        float4 gB = ldcs4(G + offB + i);
        float4 vB = ldcs4(Bc + offB + i);

        float a0 = c0 * rA.x + c1 * gA.x + c2 * vA.x;
        float a1 = c0 * rA.y + c1 * gA.y + c2 * vA.y;
        float a2 = c0 * rA.z + c1 * gA.z + c2 * vA.z;
        float a3 = c0 * rA.w + c1 * gA.w + c2 * vA.w;
        float b0 = c0 * rB.x + c1 * gB.x + c2 * vB.x;
        float b1 = c0 * rB.y + c1 * gB.y + c2 * vB.y;
        float b2 = c0 * rB.z + c1 * gB.z + c2 * vB.z;
        float b3 = c0 * rB.w + c1 * gB.w + c2 * vB.w;

        unsigned qa0 = min((unsigned)(a0 * 65536.0f), 65535u);
        unsigned qa1 = min((unsigned)(a1 * 65536.0f), 65535u);
        unsigned qa2 = min((unsigned)(a2 * 65536.0f), 65535u);
        unsigned qa3 = min((unsigned)(a3 * 65536.0f), 65535u);
        unsigned qb0 = min((unsigned)(b0 * 65536.0f), 65535u);
        unsigned qb1 = min((unsigned)(b1 * 65536.0f), 65535u);
        unsigned qb2 = min((unsigned)(b2 * 65536.0f), 65535u);
        unsigned qb3 = min((unsigned)(b3 * 65536.0f), 65535u);

        uint2 sA, sB;
        sA.x = qa0 | (qa1 << 16);
        sA.y = qa2 | (qa3 << 16);
        sB.x = qb0 | (qb1 << 16);
        sB.y = qb2 | (qb3 << 16);
        Y[offA + i] = sA;
        Y[offB + i] = sB;

        atomicAdd(&sh[qa0 >> FBITS], 1u);
        atomicAdd(&sh[qa1 >> FBITS], 1u);
        atomicAdd(&sh[qa2 >> FBITS], 1u);
        atomicAdd(&sh[qa3 >> FBITS], 1u);
        atomicAdd(&sh[qb0 >> FBITS], 1u);
        atomicAdd(&sh[qb1 >> FBITS], 1u);
        atomicAdd(&sh[qb2 >> FBITS], 1u);
        atomicAdd(&sh[qb3 >> FBITS], 1u);
    }
    __syncthreads();

    for (int j = threadIdx.x; j < CB; j += NT) {
        unsigned v = sh[j];
        if (v) atomicAdd(&g_hist[b][j], v);
    }
}

// ------------- kernel 2: coarse bin + intra-bin rank for the 4 targets -------------
__global__ void __launch_bounds__(NT) k_coarse_select() {
    __shared__ unsigned psum[NT];
    const int b = blockIdx.x;
    const unsigned* __restrict__ h = g_hist[b];
    const int W = CB / NT;                 // 16
    const int base = threadIdx.x * W;

    unsigned local = 0;
    #pragma unroll
    for (int j = 0; j < W; j++) local += h[base + j];
    psum[threadIdx.x] = local;
    __syncthreads();
    if (threadIdx.x == 0) {
        unsigned cum = 0;
        for (int i = 0; i < NT; i++) { unsigned c = psum[i]; psum[i] = cum; cum += c; }
    }
    __syncthreads();
    const unsigned pre = psum[threadIdx.x];

    const unsigned ranks[4] = {RANK0, RANK1, RANK2, RANK3};
    #pragma unroll
    for (int t = 0; t < 4; t++) {
        unsigned r = ranks[t];
        if (r >= pre && r < pre + local) {
            unsigned cum = pre;
            for (int j = 0; j < W; j++) {
                unsigned c = h[base + j];
                if (r < cum + c) {
                    g_tbin[b][t] = base + j;
                    g_trank[b][t] = (int)(r - cum);
                    break;
                }
                cum += c;
            }
        }
    }
}

// ------------- kernel 3: fine (4-bit) counts inside the 4 target coarse bins -------------
__global__ void __launch_bounds__(NT) k_fine() {
    __shared__ unsigned sf[64];
    __shared__ int stb[4];
    const int b = blockIdx.y;

    if (threadIdx.x < 64) sf[threadIdx.x] = 0u;
    if (threadIdx.x < 4) stb[threadIdx.x] = g_tbin[b][threadIdx.x];
    __syncthreads();
    const int t0 = stb[0], t1 = stb[1], t2 = stb[2], t3 = stb[3];

    const uint4* __restrict__ Y = (const uint4*)(g_Y16 + (size_t)b * HW);
    const int per_cta = (HW / 8) / CHUNKS;           // 2048 uint4
    const int off = blockIdx.x * per_cta;

    #pragma unroll 2
    for (int i = threadIdx.x; i < per_cta; i += NT) {
        uint4 x = __ldcs(Y + off + i);               // last consumer: evict-first
        unsigned w[4] = {x.x, x.y, x.z, x.w};
        #pragma unroll
        for (int k = 0; k < 4; k++) {
            unsigned vlo = w[k] & 0xffffu;
            unsigned vhi = w[k] >> 16;
            int clo = (int)(vlo >> FBITS);
            int chi = (int)(vhi >> FBITS);
            if (clo == t0) atomicAdd(&sf[ 0 + (vlo & 15u)], 1u);
            if (clo == t1) atomicAdd(&sf[16 + (vlo & 15u)], 1u);
            if (clo == t2) atomicAdd(&sf[32 + (vlo & 15u)], 1u);
            if (clo == t3) atomicAdd(&sf[48 + (vlo & 15u)], 1u);
            if (chi == t0) atomicAdd(&sf[ 0 + (vhi & 15u)], 1u);
            if (chi == t1) atomicAdd(&sf[16 + (vhi & 15u)], 1u);
            if (chi == t2) atomicAdd(&sf[32 + (vhi & 15u)], 1u);
            if (chi == t3) atomicAdd(&sf[48 + (vhi & 15u)], 1u);
        }
    }
    __syncthreads();
    if (threadIdx.x < 64) {
        unsigned v = sf[threadIdx.x];
        if (v) atomicAdd(&((unsigned*)g_hist2[b])[threadIdx.x], v);
    }
}

// ------------- kernel 4: per-CTA redundant fine select, then apply. Zeroes g_hist. -------------
__global__ void __launch_bounds__(NT) k_apply(const float* __restrict__ img,
                                              float* __restrict__ out) {
    __shared__ float s_vals[4];
    __shared__ float s_bm[2];
    const int b = blockIdx.y;
    const int tid = threadIdx.x;

    // zero coarse hist for the next replay (fine+coarse_select already consumed it)
    {
        int cta = blockIdx.y * gridDim.x + blockIdx.x;
        if (cta < 256) ((unsigned*)g_hist)[cta * 256 + tid] = 0u;
    }

    // redundant select: threads 0..63 = (target t = tid>>4, fine bin j = tid&15)
    if (tid < 64) {
        const int t = tid >> 4;
        const int j = tid & 15;
        unsigned c = g_hist2[b][t][j];
        unsigned p = c;
        #pragma unroll
        for (int d = 1; d < 16; d <<= 1) {
            unsigned o = __shfl_up_sync(0xffffffffu, p, d, 16);
            if ((tid & 15) >= d) p += o;
        }
        unsigned pre = p - c;
        unsigned tr = (unsigned)g_trank[b][t];
        if (tr >= pre && tr < pre + c) {
            unsigned q = ((unsigned)g_tbin[b][t] << FBITS) | (unsigned)j;
            s_vals[t] = ((float)q + 0.5f) * (1.0f / 65536.0f);
        }
    }
    __syncthreads();
    if (tid == 0) {
        float blk = 0.25f * s_vals[0] + 0.75f * s_vals[1];
        float wht = 0.75f * s_vals[2] + 0.25f * s_vals[3];
        s_bm[0] = blk;
        s_bm[1] = fminf(1.0f / (wht - blk), 1.5f);
    }
    __syncthreads();
    const float blk = s_bm[0];
    const float m = s_bm[1];

    const size_t base = (size_t)b * 3 * (HW / 4);
    const float4* __restrict__ in4 = (const float4*)img + base;
    float4* __restrict__ o4 = (float4*)out + base;
    const int n = 3 * (HW / 4);
    const int stride = gridDim.x * NT;

    for (int i = blockIdx.x * NT + tid; i < n; i += stride) {
        float4 v = __ldcs(in4 + i);
        float4 r;
        r.x = fminf(fmaxf((v.x - blk) * m, 0.0f), 1.0f);
        r.y = fminf(fmaxf((v.y - blk) * m, 0.0f), 1.0f);
        r.z = fminf(fmaxf((v.z - blk) * m, 0.0f), 1.0f);
        r.w = fminf(fmaxf((v.w - blk) * m, 0.0f), 1.0f);
        __stcs(o4 + i, r);
    }
}

// ---------------- launch ----------------
extern "C" void kernel_launch(void* const* d_in, const int* in_sizes, int n_in,
                              void* d_out, int out_size) {
    const float* img = (const float*)d_in[0];
    const float* mat = (const float*)d_in[1];
    float* out = (float*)d_out;

    dim3 gBig(CHUNKS, BATCH);
    k_yhist<<<gBig, NT>>>(img, mat);
    k_coarse_select<<<BATCH, NT>>>();
    k_fine<<<gBig, NT>>>();
    dim3 gApply(384, BATCH);
    k_apply<<<gApply, NT>>>(img, out);
}

// round 5
// speedup vs baseline: 1.0572x; 1.0572x over previous
#include <cuda_runtime.h>

#define BATCH 16
#define HW (1 << 20)
#define CB 4096                 // coarse bins (q >> 4)
#define FBITS 4                 // fine bins = 16 (q & 15)
#define CHUNKS 64
#define NT 256

// percentile ranks, n = 1048576 (linear interp):
// blk: 0.25*v[10485] + 0.75*v[10486] ; wht: 0.75*v[1038089] + 0.25*v[1038090]
#define RANK0 10485u
#define RANK1 10486u
#define RANK2 1038089u
#define RANK3 1038090u

// ---------------- device scratch ----------------
__device__ unsigned short g_Y16[(size_t)BATCH * HW];   // 32 MB quantized luma
__device__ unsigned g_hist[BATCH][CB];                 // coarse hists
__device__ unsigned g_hist2[BATCH][4][16];             // fine hists (tiny)
__device__ int      g_tbin[BATCH][4];
__device__ int      g_trank[BATCH][4];

// ------------- kernel 1: Y16 + coarse hist (zeroes g_hist2 for this replay) -------------
// Two independent streams per thread for doubled MLP (R3-measured: 44.4us).
__global__ void __launch_bounds__(NT) k_yhist(const float* __restrict__ img,
                                              const float* __restrict__ mat) {
    __shared__ unsigned sh[CB];
    const int b = blockIdx.y;
    const int chunk = blockIdx.x;

    if (blockIdx.x == 0 && threadIdx.x < 64)
        ((unsigned*)g_hist2[b])[threadIdx.x] = 0u;

    for (int j = threadIdx.x; j < CB; j += NT) sh[j] = 0u;
    __syncthreads();

    const float c0 = mat[0], c1 = mat[1], c2 = mat[2];
    const size_t base = (size_t)b * 3 * HW;
    const float4* __restrict__ R  = (const float4*)(img + base);
    const float4* __restrict__ G  = (const float4*)(img + base + HW);
    const float4* __restrict__ Bc = (const float4*)(img + base + 2 * (size_t)HW);
    uint2* __restrict__ Y = (uint2*)(g_Y16 + (size_t)b * HW);

    const int per_cta = (HW / 4) / CHUNKS;   // 4096 float4
    const int half = per_cta / 2;            // 2048
    const int offA = chunk * per_cta;
    const int offB = offA + half;

    #pragma unroll 2
    for (int i = threadIdx.x; i < half; i += NT) {
        // stream A
        float4 rA = R[offA + i];
        float4 gA = G[offA + i];
        float4 vA = Bc[offA + i];
        // stream B
        float4 rB = R[offB + i];
        float4 gB = G[offB + i];
        float4 vB = Bc[offB + i];

        float a0 = c0 * rA.x + c1 * gA.x + c2 * vA.x;
        float a1 = c0 * rA.y + c1 * gA.y + c2 * vA.y;
        float a2 = c0 * rA.z + c1 * gA.z + c2 * vA.z;
        float a3 = c0 * rA.w + c1 * gA.w + c2 * vA.w;
        float b0 = c0 * rB.x + c1 * gB.x + c2 * vB.x;
        float b1 = c0 * rB.y + c1 * gB.y + c2 * vB.y;
        float b2 = c0 * rB.z + c1 * gB.z + c2 * vB.z;
        float b3 = c0 * rB.w + c1 * gB.w + c2 * vB.w;

        unsigned qa0 = min((unsigned)(a0 * 65536.0f), 65535u);
        unsigned qa1 = min((unsigned)(a1 * 65536.0f), 65535u);
        unsigned qa2 = min((unsigned)(a2 * 65536.0f), 65535u);
        unsigned qa3 = min((unsigned)(a3 * 65536.0f), 65535u);
        unsigned qb0 = min((unsigned)(b0 * 65536.0f), 65535u);
        unsigned qb1 = min((unsigned)(b1 * 65536.0f), 65535u);
        unsigned qb2 = min((unsigned)(b2 * 65536.0f), 65535u);
        unsigned qb3 = min((unsigned)(b3 * 65536.0f), 65535u);

        uint2 sA, sB;
        sA.x = qa0 | (qa1 << 16);
        sA.y = qa2 | (qa3 << 16);
        sB.x = qb0 | (qb1 << 16);
        sB.y = qb2 | (qb3 << 16);
        Y[offA + i] = sA;
        Y[offB + i] = sB;

        atomicAdd(&sh[qa0 >> FBITS], 1u);
        atomicAdd(&sh[qa1 >> FBITS], 1u);
        atomicAdd(&sh[qa2 >> FBITS], 1u);
        atomicAdd(&sh[qa3 >> FBITS], 1u);
        atomicAdd(&sh[qb0 >> FBITS], 1u);
        atomicAdd(&sh[qb1 >> FBITS], 1u);
        atomicAdd(&sh[qb2 >> FBITS], 1u);
        atomicAdd(&sh[qb3 >> FBITS], 1u);
    }
    __syncthreads();

    for (int j = threadIdx.x; j < CB; j += NT) {
        unsigned v = sh[j];
        if (v) atomicAdd(&g_hist[b][j], v);
    }
}

// ------------- kernel 2: coarse bin + intra-bin rank for the 4 targets -------------
__global__ void __launch_bounds__(NT) k_coarse_select() {
    __shared__ unsigned psum[NT];
    const int b = blockIdx.x;
    const unsigned* __restrict__ h = g_hist[b];
    const int W = CB / NT;                 // 16
    const int base = threadIdx.x * W;

    unsigned local = 0;
    #pragma unroll
    for (int j = 0; j < W; j++) local += h[base + j];
    psum[threadIdx.x] = local;
    __syncthreads();
    if (threadIdx.x == 0) {
        unsigned cum = 0;
        for (int i = 0; i < NT; i++) { unsigned c = psum[i]; psum[i] = cum; cum += c; }
    }
    __syncthreads();
    const unsigned pre = psum[threadIdx.x];

    const unsigned ranks[4] = {RANK0, RANK1, RANK2, RANK3};
    #pragma unroll
    for (int t = 0; t < 4; t++) {
        unsigned r = ranks[t];
        if (r >= pre && r < pre + local) {
            unsigned cum = pre;
            for (int j = 0; j < W; j++) {
                unsigned c = h[base + j];
                if (r < cum + c) {
                    g_tbin[b][t] = base + j;
                    g_trank[b][t] = (int)(r - cum);
                    break;
                }
                cum += c;
            }
        }
    }
}

// ------------- kernel 3: fine (4-bit) counts inside the 4 target coarse bins -------------
__global__ void __launch_bounds__(NT) k_fine() {
    __shared__ unsigned sf[64];
    __shared__ int stb[4];
    const int b = blockIdx.y;

    if (threadIdx.x < 64) sf[threadIdx.x] = 0u;
    if (threadIdx.x < 4) stb[threadIdx.x] = g_tbin[b][threadIdx.x];
    __syncthreads();
    const int t0 = stb[0], t1 = stb[1], t2 = stb[2], t3 = stb[3];

    const uint4* __restrict__ Y = (const uint4*)(g_Y16 + (size_t)b * HW);
    const int per_cta = (HW / 8) / CHUNKS;           // 2048 uint4
    const int off = blockIdx.x * per_cta;

    #pragma unroll 2
    for (int i = threadIdx.x; i < per_cta; i += NT) {
        uint4 x = Y[off + i];
        unsigned w[4] = {x.x, x.y, x.z, x.w};
        #pragma unroll
        for (int k = 0; k < 4; k++) {
            unsigned vlo = w[k] & 0xffffu;
            unsigned vhi = w[k] >> 16;
            int clo = (int)(vlo >> FBITS);
            int chi = (int)(vhi >> FBITS);
            if (clo == t0) atomicAdd(&sf[ 0 + (vlo & 15u)], 1u);
            if (clo == t1) atomicAdd(&sf[16 + (vlo & 15u)], 1u);
            if (clo == t2) atomicAdd(&sf[32 + (vlo & 15u)], 1u);
            if (clo == t3) atomicAdd(&sf[48 + (vlo & 15u)], 1u);
            if (chi == t0) atomicAdd(&sf[ 0 + (vhi & 15u)], 1u);
            if (chi == t1) atomicAdd(&sf[16 + (vhi & 15u)], 1u);
            if (chi == t2) atomicAdd(&sf[32 + (vhi & 15u)], 1u);
            if (chi == t3) atomicAdd(&sf[48 + (vhi & 15u)], 1u);
        }
    }
    __syncthreads();
    if (threadIdx.x < 64) {
        unsigned v = sf[threadIdx.x];
        if (v) atomicAdd(&((unsigned*)g_hist2[b])[threadIdx.x], v);
    }
}

// ------------- kernel 4: per-CTA redundant fine select, then apply. Zeroes g_hist. -------------
__global__ void __launch_bounds__(NT) k_apply(const float* __restrict__ img,
                                              float* __restrict__ out) {
    __shared__ float s_vals[4];
    __shared__ float s_bm[2];
    const int b = blockIdx.y;
    const int tid = threadIdx.x;

    // zero coarse hist for the next replay (fine+coarse_select already consumed it)
    {
        int cta = blockIdx.y * gridDim.x + blockIdx.x;
        if (cta < 256) ((unsigned*)g_hist)[cta * 256 + tid] = 0u;
    }

    // redundant select: threads 0..63 = (target t = tid>>4, fine bin j = tid&15)
    if (tid < 64) {
        const int t = tid >> 4;
        const int j = tid & 15;
        unsigned c = g_hist2[b][t][j];
        unsigned p = c;
        #pragma unroll
        for (int d = 1; d < 16; d <<= 1) {
            unsigned o = __shfl_up_sync(0xffffffffu, p, d, 16);
            if ((tid & 15) >= d) p += o;
        }
        unsigned pre = p - c;
        unsigned tr = (unsigned)g_trank[b][t];
        if (tr >= pre && tr < pre + c) {
            unsigned q = ((unsigned)g_tbin[b][t] << FBITS) | (unsigned)j;
            s_vals[t] = ((float)q + 0.5f) * (1.0f / 65536.0f);
        }
    }
    __syncthreads();
    if (tid == 0) {
        float blk = 0.25f * s_vals[0] + 0.75f * s_vals[1];
        float wht = 0.75f * s_vals[2] + 0.25f * s_vals[3];
        s_bm[0] = blk;
        s_bm[1] = fminf(1.0f / (wht - blk), 1.5f);
    }
    __syncthreads();
    const float blk = s_bm[0];
    const float m = s_bm[1];

    const size_t base = (size_t)b * 3 * (HW / 4);
    const float4* __restrict__ in4 = (const float4*)img + base;
    float4* __restrict__ o4 = (float4*)out + base;
    const int n = 3 * (HW / 4);
    const int stride = gridDim.x * NT;

    for (int i = blockIdx.x * NT + tid; i < n; i += stride) {
        float4 v = in4[i];
        float4 r;
        r.x = fminf(fmaxf((v.x - blk) * m, 0.0f), 1.0f);
        r.y = fminf(fmaxf((v.y - blk) * m, 0.0f), 1.0f);
        r.z = fminf(fmaxf((v.z - blk) * m, 0.0f), 1.0f);
        r.w = fminf(fmaxf((v.w - blk) * m, 0.0f), 1.0f);
        o4[i] = r;
    }
}

// ---------------- launch ----------------
extern "C" void kernel_launch(void* const* d_in, const int* in_sizes, int n_in,
                              void* d_out, int out_size) {
    const float* img = (const float*)d_in[0];
    const float* mat = (const float*)d_in[1];
    float* out = (float*)d_out;

    dim3 gBig(CHUNKS, BATCH);
    k_yhist<<<gBig, NT>>>(img, mat);
    k_coarse_select<<<BATCH, NT>>>();
    k_fine<<<gBig, NT>>>();
    dim3 gApply(384, BATCH);
    k_apply<<<gApply, NT>>>(img, out);
}